// round 2
// baseline (speedup 1.0000x reference)
#include <cuda_runtime.h>
#include <cuda_fp16.h>
#include <cstdint>
#include <cstddef>

// ============================================================
// Problem geometry: out[16384,4096] = X[16384,4096] @ W[4096,4096]^T
// W = (w_pos>0) - (w_neg>0)  in {-1,0,+1}  (exact in fp16)
// ============================================================
#define M_TOTAL 16384
#define N_TOTAL 4096
#define K_TOTAL 4096

#define TILE_M 128
#define TILE_N 128
#define TILE_K 64                         // 64 fp16 = 128B rows (SW128 atom)
#define STAGES 4
#define NCHUNK (K_TOTAL / TILE_K)         // 64
#define N_TILES (N_TOTAL / TILE_N)        // 32
#define M_TILES (M_TOTAL / TILE_M)        // 128

#define A_BYTES (TILE_M * TILE_K * 2)     // 16384
#define B_BYTES (TILE_N * TILE_K * 2)     // 16384
#define STAGE_BYTES (A_BYTES + B_BYTES)   // 32768
#define SMEM_TOTAL (STAGES * STAGE_BYTES) // 131072

// Scratch (device globals: allocation-free rule)
__device__ __align__(128) __half g_W[(size_t)N_TOTAL * K_TOTAL];  // [N,K] 32 MB
__device__ __align__(128) __half g_X[(size_t)M_TOTAL * K_TOTAL];  // [M,K] 128 MB

// ============================================================
// Base-ISA PTX helpers (sm_80-era: safe at target sm_103)
// ============================================================
__device__ __forceinline__ uint32_t smem_u32(const void* p) {
    uint32_t a;
    asm("{ .reg .u64 t; cvta.to.shared.u64 t, %1; cvt.u32.u64 %0, t; }"
        : "=r"(a) : "l"(p));
    return a;
}

#define CP_ASYNC16(dst_u32, src_ptr) \
    asm volatile("cp.async.cg.shared.global [%0], [%1], 16;" \
                 :: "r"(dst_u32), "l"(src_ptr) : "memory")
#define CP_COMMIT() asm volatile("cp.async.commit_group;" ::: "memory")
#define CP_WAIT(n)  asm volatile("cp.async.wait_group %0;" :: "n"(n) : "memory")

__device__ __forceinline__ void ldsm4(uint32_t& r0, uint32_t& r1,
                                      uint32_t& r2, uint32_t& r3, uint32_t addr) {
    asm volatile("ldmatrix.sync.aligned.m8n8.x4.shared.b16 {%0,%1,%2,%3}, [%4];"
                 : "=r"(r0), "=r"(r1), "=r"(r2), "=r"(r3) : "r"(addr));
}

__device__ __forceinline__ void mma16816(float* d, const uint32_t* a,
                                         uint32_t b0, uint32_t b1) {
    asm volatile(
        "mma.sync.aligned.m16n8k16.row.col.f32.f16.f16.f32 "
        "{%0,%1,%2,%3}, {%4,%5,%6,%7}, {%8,%9}, {%0,%1,%2,%3};"
        : "+f"(d[0]), "+f"(d[1]), "+f"(d[2]), "+f"(d[3])
        : "r"(a[0]), "r"(a[1]), "r"(a[2]), "r"(a[3]), "r"(b0), "r"(b1));
}

// SW128 swizzle: off ^ ((off>>3)&0x70)  (Swizzle<3,4,3>, ldmatrix conflict-free)
__device__ __forceinline__ uint32_t sw128(uint32_t off) {
    return off ^ ((off >> 3) & 0x70u);
}

// ============================================================
// Prep kernels
// ============================================================
__global__ void k_cvt_x(const float4* __restrict__ x, int n4) {
    int i = blockIdx.x * blockDim.x + threadIdx.x;
    if (i < n4) {
        float4 v = x[i];
        __half2* dst = (__half2*)g_X;
        dst[2 * i + 0] = __floats2half2_rn(v.x, v.y);
        dst[2 * i + 1] = __floats2half2_rn(v.z, v.w);
    }
}

__global__ void k_binarize_w(const float4* __restrict__ wp,
                             const float4* __restrict__ wn, int n4) {
    int i = blockIdx.x * blockDim.x + threadIdx.x;
    if (i < n4) {
        float4 p = wp[i];
        float4 n = wn[i];
        float a = (float)((p.x > 0.f) - (n.x > 0.f));
        float b = (float)((p.y > 0.f) - (n.y > 0.f));
        float c = (float)((p.z > 0.f) - (n.z > 0.f));
        float d = (float)((p.w > 0.f) - (n.w > 0.f));
        __half2* dst = (__half2*)g_W;
        dst[2 * i + 0] = __floats2half2_rn(a, b);
        dst[2 * i + 1] = __floats2half2_rn(c, d);
    }
}

// ============================================================
// GEMM mainloop
// ============================================================
// Per-thread cp.async for one stage: thread t covers A row t/2 (4x16B) and
// B row t/2 (4x16B), second half of the 8 chunks selected by t&1.
__device__ __forceinline__ void issue_tile_loads(
    uint32_t smem_base, int s, int kc, int m0, int n0, int tid)
{
    uint32_t sa = smem_base + (uint32_t)s * STAGE_BYTES;
    uint32_t sb = sa + A_BYTES;
    const int row = tid >> 1;
    const int c0  = (tid & 1) * 4;
    const char* srcA = (const char*)(g_X + (size_t)(m0 + row) * K_TOTAL + kc * TILE_K);
    const char* srcB = (const char*)(g_W + (size_t)(n0 + row) * K_TOTAL + kc * TILE_K);
    uint32_t rb = (uint32_t)row * 128u;
    #pragma unroll
    for (int c = 0; c < 4; c++) {
        uint32_t off = rb + (uint32_t)(c0 + c) * 16u;
        CP_ASYNC16(sa + sw128(off), srcA + (c0 + c) * 16);
    }
    #pragma unroll
    for (int c = 0; c < 4; c++) {
        uint32_t off = rb + (uint32_t)(c0 + c) * 16u;
        CP_ASYNC16(sb + sw128(off), srcB + (c0 + c) * 16);
    }
}

__global__ void __launch_bounds__(256, 1) plinear_gemm(float* __restrict__ out) {
    extern __shared__ char smem[];
    uint32_t smem_base = smem_u32(smem);
    const int tid = threadIdx.x;
    const int wid = tid >> 5;
    const int lid = tid & 31;

    // N-fast ordering: a wave shares X tiles; all of W stays L2-resident
    const int nt = blockIdx.x & (N_TILES - 1);
    const int mt = blockIdx.x >> 5;
    const int m0 = mt * TILE_M;
    const int n0 = nt * TILE_N;

    // warp grid 4(M) x 2(N): warp tile 32 x 64
    const int mwarp = (wid >> 1) * 32;
    const int nwarp = (wid & 1) * 64;

    float acc[2][8][4];
    #pragma unroll
    for (int i = 0; i < 2; i++)
        #pragma unroll
        for (int j = 0; j < 8; j++)
            #pragma unroll
            for (int c = 0; c < 4; c++) acc[i][j][c] = 0.f;

    // ldmatrix per-thread addresses (byte offsets within tile, pre-swizzled later)
    // A (row-major m16k16, .x4): row = base + (l&7) + ((l>>3)&1)*8 ; col = (l>>4)*16
    const int a_r = (lid & 7) + (((lid >> 3) & 1) << 3);
    const int a_c = (lid >> 4) << 4;
    // B ([n][k] rows, .x4 over n16): row = base + (l&7) + (l>>4)*8 ; col = ((l>>3)&1)*16
    const int b_r = (lid & 7) + ((lid >> 4) << 3);
    const int b_c = ((lid >> 3) & 1) << 4;

    // Prologue: stages 0..2
    issue_tile_loads(smem_base, 0, 0, m0, n0, tid); CP_COMMIT();
    issue_tile_loads(smem_base, 1, 1, m0, n0, tid); CP_COMMIT();
    issue_tile_loads(smem_base, 2, 2, m0, n0, tid); CP_COMMIT();

    #pragma unroll 1
    for (int kc = 0; kc < NCHUNK; kc++) {
        // Prefetch kc+3 into stage (kc+3)&3 (= stage of chunk kc-1, whose reads
        // finished before last iteration's trailing barrier)
        const int pf = kc + 3;
        if (pf < NCHUNK)
            issue_tile_loads(smem_base, pf & (STAGES - 1), pf, m0, n0, tid);
        CP_COMMIT();
        CP_WAIT(3);              // groups kc+1..kc+3 may remain: stage kc ready
        __syncthreads();

        const uint32_t sa = smem_base + (uint32_t)(kc & (STAGES - 1)) * STAGE_BYTES;
        const uint32_t sb = sa + A_BYTES;

        #pragma unroll
        for (int ks = 0; ks < 4; ks++) {
            const int kb = ks * 32;      // byte col of this k16 step
            uint32_t a[2][4];
            #pragma unroll
            for (int i = 0; i < 2; i++) {
                uint32_t off = (uint32_t)(mwarp + i * 16 + a_r) * 128u + (kb + a_c);
                ldsm4(a[i][0], a[i][1], a[i][2], a[i][3], sa + sw128(off));
            }
            uint32_t b[4][4];
            #pragma unroll
            for (int j = 0; j < 4; j++) {
                uint32_t off = (uint32_t)(nwarp + j * 16 + b_r) * 128u + (kb + b_c);
                ldsm4(b[j][0], b[j][1], b[j][2], b[j][3], sb + sw128(off));
            }
            #pragma unroll
            for (int i = 0; i < 2; i++)
                #pragma unroll
                for (int j = 0; j < 4; j++) {
                    mma16816(acc[i][2 * j + 0], a[i], b[j][0], b[j][1]);
                    mma16816(acc[i][2 * j + 1], a[i], b[j][2], b[j][3]);
                }
        }
        __syncthreads();
    }

    // Epilogue: direct f32 stores. C-frag: c0,c1 -> row g, cols t2,t2+1; c2,c3 -> row g+8
    {
        const int g  = lid >> 2;
        const int t2 = (lid & 3) * 2;
        #pragma unroll
        for (int i = 0; i < 2; i++) {
            float* r0 = out + (size_t)(m0 + mwarp + i * 16 + g) * N_TOTAL + n0 + nwarp + t2;
            float* r1 = r0 + 8 * N_TOTAL;
            #pragma unroll
            for (int j = 0; j < 8; j++) {
                *(float2*)(r0 + j * 8) = make_float2(acc[i][j][0], acc[i][j][1]);
                *(float2*)(r1 + j * 8) = make_float2(acc[i][j][2], acc[i][j][3]);
            }
        }
    }
}

// ============================================================
// Launch
// ============================================================
extern "C" void kernel_launch(void* const* d_in, const int* in_sizes, int n_in,
                              void* d_out, int out_size) {
    const float* x  = (const float*)d_in[0];
    const float* wp = (const float*)d_in[1];
    const float* wn = (const float*)d_in[2];
    float* out = (float*)d_out;

    cudaFuncSetAttribute(plinear_gemm,
                         cudaFuncAttributeMaxDynamicSharedMemorySize, SMEM_TOTAL);

    const int n4x = (M_TOTAL * K_TOTAL) / 4;
    const int n4w = (N_TOTAL * K_TOTAL) / 4;
    k_cvt_x<<<n4x / 256, 256>>>((const float4*)x, n4x);
    k_binarize_w<<<n4w / 256, 256>>>((const float4*)wp, (const float4*)wn, n4w);

    plinear_gemm<<<M_TILES * N_TILES, 256, SMEM_TOTAL>>>(out);
}

// round 3
// speedup vs baseline: 1.1587x; 1.1587x over previous
#include <cuda_runtime.h>
#include <cuda_fp16.h>
#include <cstdint>
#include <cstddef>

// ============================================================
// out[16384,4096] = X[16384,4096] @ W[4096,4096]^T
// W = (w_pos>0) - (w_neg>0)  in {-1,0,+1}  (exact in fp16)
// CTA tile 128x256xK64, 8 warps (2x4), warp tile 64x64, 4-stage cp.async
// ============================================================
#define M_TOTAL 16384
#define N_TOTAL 4096
#define K_TOTAL 4096

#define TILE_M 128
#define TILE_N 256
#define TILE_K 64                         // 128B rows (SW128 atom)
#define STAGES 4
#define NCHUNK (K_TOTAL / TILE_K)         // 64
#define N_TILES (N_TOTAL / TILE_N)        // 16
#define M_TILES (M_TOTAL / TILE_M)        // 128

#define A_BYTES (TILE_M * TILE_K * 2)     // 16384
#define B_BYTES (TILE_N * TILE_K * 2)     // 32768
#define STAGE_BYTES (A_BYTES + B_BYTES)   // 49152
#define SMEM_TOTAL (STAGES * STAGE_BYTES) // 196608

// Scratch (device globals: allocation-free rule)
__device__ __align__(128) __half g_W[(size_t)N_TOTAL * K_TOTAL];  // [N,K] 32 MB
__device__ __align__(128) __half g_X[(size_t)M_TOTAL * K_TOTAL];  // [M,K] 128 MB

// ============================================================
// Base-ISA PTX helpers
// ============================================================
__device__ __forceinline__ uint32_t smem_u32(const void* p) {
    uint32_t a;
    asm("{ .reg .u64 t; cvta.to.shared.u64 t, %1; cvt.u32.u64 %0, t; }"
        : "=r"(a) : "l"(p));
    return a;
}

#define CP_ASYNC16(dst_u32, src_ptr) \
    asm volatile("cp.async.cg.shared.global [%0], [%1], 16;" \
                 :: "r"(dst_u32), "l"(src_ptr) : "memory")
#define CP_COMMIT() asm volatile("cp.async.commit_group;" ::: "memory")
#define CP_WAIT(n)  asm volatile("cp.async.wait_group %0;" :: "n"(n) : "memory")

__device__ __forceinline__ void ldsm4(uint32_t& r0, uint32_t& r1,
                                      uint32_t& r2, uint32_t& r3, uint32_t addr) {
    asm volatile("ldmatrix.sync.aligned.m8n8.x4.shared.b16 {%0,%1,%2,%3}, [%4];"
                 : "=r"(r0), "=r"(r1), "=r"(r2), "=r"(r3) : "r"(addr));
}

__device__ __forceinline__ void mma16816(float* d, const uint32_t* a,
                                         uint32_t b0, uint32_t b1) {
    asm volatile(
        "mma.sync.aligned.m16n8k16.row.col.f32.f16.f16.f32 "
        "{%0,%1,%2,%3}, {%4,%5,%6,%7}, {%8,%9}, {%0,%1,%2,%3};"
        : "+f"(d[0]), "+f"(d[1]), "+f"(d[2]), "+f"(d[3])
        : "r"(a[0]), "r"(a[1]), "r"(a[2]), "r"(a[3]), "r"(b0), "r"(b1));
}

__device__ __forceinline__ uint32_t sw128(uint32_t off) {
    return off ^ ((off >> 3) & 0x70u);
}

// ============================================================
// Prep kernels
// ============================================================
__global__ void k_cvt_x(const float4* __restrict__ x, int n4) {
    int i = blockIdx.x * blockDim.x + threadIdx.x;
    if (i < n4) {
        float4 v = x[i];
        __half2* dst = (__half2*)g_X;
        dst[2 * i + 0] = __floats2half2_rn(v.x, v.y);
        dst[2 * i + 1] = __floats2half2_rn(v.z, v.w);
    }
}

__global__ void k_binarize_w(const float4* __restrict__ wp,
                             const float4* __restrict__ wn, int n4) {
    int i = blockIdx.x * blockDim.x + threadIdx.x;
    if (i < n4) {
        float4 p = wp[i];
        float4 n = wn[i];
        float a = (float)((p.x > 0.f) - (n.x > 0.f));
        float b = (float)((p.y > 0.f) - (n.y > 0.f));
        float c = (float)((p.z > 0.f) - (n.z > 0.f));
        float d = (float)((p.w > 0.f) - (n.w > 0.f));
        __half2* dst = (__half2*)g_W;
        dst[2 * i + 0] = __floats2half2_rn(a, b);
        dst[2 * i + 1] = __floats2half2_rn(c, d);
    }
}

// ============================================================
// GEMM mainloop
// ============================================================
// Stage fill: A 128 rows (thread t -> row t>>1, 4x16B), B 256 rows
// (thread t -> rows t>>1 and (t>>1)+128, 4x16B each). 12 cp.async / thread.
__device__ __forceinline__ void issue_tile_loads(
    uint32_t smem_base, int s, int kc, int m0, int n0, int tid)
{
    uint32_t sa = smem_base + (uint32_t)s * STAGE_BYTES;
    uint32_t sb = sa + A_BYTES;
    const int row = tid >> 1;
    const int c0  = (tid & 1) * 4;
    const char* srcA = (const char*)(g_X + (size_t)(m0 + row) * K_TOTAL + kc * TILE_K);
    uint32_t rb = (uint32_t)row * 128u;
    #pragma unroll
    for (int c = 0; c < 4; c++) {
        uint32_t off = rb + (uint32_t)(c0 + c) * 16u;
        CP_ASYNC16(sa + sw128(off), srcA + (c0 + c) * 16);
    }
    #pragma unroll
    for (int rr = 0; rr < 2; rr++) {
        const int brow = row + rr * 128;
        const char* srcB = (const char*)(g_W + (size_t)(n0 + brow) * K_TOTAL + kc * TILE_K);
        uint32_t bb = (uint32_t)brow * 128u;
        #pragma unroll
        for (int c = 0; c < 4; c++) {
            uint32_t off = bb + (uint32_t)(c0 + c) * 16u;
            CP_ASYNC16(sb + sw128(off), srcB + (c0 + c) * 16);
        }
    }
}

__global__ void __launch_bounds__(256, 1) plinear_gemm(float* __restrict__ out) {
    extern __shared__ char smem[];
    uint32_t smem_base = smem_u32(smem);
    const int tid = threadIdx.x;
    const int wid = tid >> 5;
    const int lid = tid & 31;

    // N-fast ordering: wave shares X tiles; W stays L2-resident
    const int nt = blockIdx.x & (N_TILES - 1);
    const int mt = blockIdx.x >> 4;
    const int m0 = mt * TILE_M;
    const int n0 = nt * TILE_N;

    // warp grid 2(M) x 4(N): warp tile 64 x 64
    const int mwarp = (wid >> 2) * 64;
    const int nwarp = (wid & 3) * 64;

    float acc[4][8][4];
    #pragma unroll
    for (int i = 0; i < 4; i++)
        #pragma unroll
        for (int j = 0; j < 8; j++)
            #pragma unroll
            for (int c = 0; c < 4; c++) acc[i][j][c] = 0.f;

    // ldmatrix lane addressing
    const int a_r = (lid & 7) + (((lid >> 3) & 1) << 3);
    const int a_c = (lid >> 4) << 4;
    const int b_r = (lid & 7) + ((lid >> 4) << 3);
    const int b_c = ((lid >> 3) & 1) << 4;

    // Prologue: stages 0..2
    issue_tile_loads(smem_base, 0, 0, m0, n0, tid); CP_COMMIT();
    issue_tile_loads(smem_base, 1, 1, m0, n0, tid); CP_COMMIT();
    issue_tile_loads(smem_base, 2, 2, m0, n0, tid); CP_COMMIT();

    #pragma unroll 1
    for (int kc = 0; kc < NCHUNK; kc++) {
        CP_WAIT(2);          // stage kc arrived (groups kc+1,kc+2 may be pending)
        __syncthreads();     // + all reads of stage kc-1 are done (prev iter)

        // Prefetch kc+3 into stage (kc+3)&3 == (kc-1)&3 (safe after barrier)
        const int pf = kc + 3;
        if (pf < NCHUNK)
            issue_tile_loads(smem_base, pf & (STAGES - 1), pf, m0, n0, tid);
        CP_COMMIT();

        const uint32_t sa = smem_base + (uint32_t)(kc & (STAGES - 1)) * STAGE_BYTES;
        const uint32_t sb = sa + A_BYTES;

        #pragma unroll
        for (int ks = 0; ks < 4; ks++) {
            const int kb = ks * 32;             // byte col of this k16 step
            uint32_t a[4][4];
            #pragma unroll
            for (int i = 0; i < 4; i++) {
                uint32_t off = (uint32_t)(mwarp + i * 16 + a_r) * 128u + (kb + a_c);
                ldsm4(a[i][0], a[i][1], a[i][2], a[i][3], sa + sw128(off));
            }
            uint32_t b[4][4];
            #pragma unroll
            for (int j = 0; j < 4; j++) {
                uint32_t off = (uint32_t)(nwarp + j * 16 + b_r) * 128u + (kb + b_c);
                ldsm4(b[j][0], b[j][1], b[j][2], b[j][3], sb + sw128(off));
            }
            #pragma unroll
            for (int i = 0; i < 4; i++)
                #pragma unroll
                for (int j = 0; j < 4; j++) {
                    mma16816(acc[i][2 * j + 0], a[i], b[j][0], b[j][1]);
                    mma16816(acc[i][2 * j + 1], a[i], b[j][2], b[j][3]);
                }
        }
    }

    // Epilogue: f32 stores. Frag c0,c1 -> row g cols t2,t2+1; c2,c3 -> row g+8.
    {
        const int g  = lid >> 2;
        const int t2 = (lid & 3) * 2;
        #pragma unroll
        for (int i = 0; i < 4; i++) {
            float* r0 = out + (size_t)(m0 + mwarp + i * 16 + g) * N_TOTAL + n0 + nwarp + t2;
            float* r1 = r0 + 8 * N_TOTAL;
            #pragma unroll
            for (int j = 0; j < 8; j++) {
                *(float2*)(r0 + j * 8) = make_float2(acc[i][j][0], acc[i][j][1]);
                *(float2*)(r1 + j * 8) = make_float2(acc[i][j][2], acc[i][j][3]);
            }
        }
    }
}

// ============================================================
// Launch
// ============================================================
extern "C" void kernel_launch(void* const* d_in, const int* in_sizes, int n_in,
                              void* d_out, int out_size) {
    const float* x  = (const float*)d_in[0];
    const float* wp = (const float*)d_in[1];
    const float* wn = (const float*)d_in[2];
    float* out = (float*)d_out;

    cudaFuncSetAttribute(plinear_gemm,
                         cudaFuncAttributeMaxDynamicSharedMemorySize, SMEM_TOTAL);

    const int n4x = (M_TOTAL * K_TOTAL) / 4;
    const int n4w = (N_TOTAL * K_TOTAL) / 4;
    k_cvt_x<<<n4x / 256, 256>>>((const float4*)x, n4x);
    k_binarize_w<<<n4w / 256, 256>>>((const float4*)wp, (const float4*)wn, n4w);

    plinear_gemm<<<M_TILES * N_TILES, 256, SMEM_TOTAL>>>(out);
}